// round 7
// baseline (speedup 1.0000x reference)
#include <cuda_runtime.h>

#define HW 262144      // 512*512
#define W  512

// cos(k*pi/16)
#define C1f 0.98078528040323044913f
#define C2f 0.92387953251128675613f
#define C3f 0.83146961230254523708f
#define C4f 0.70710678118654752440f
#define C5f 0.55557023301960222474f
#define C6f 0.38268343236508977173f
#define C7f 0.19509032201612826785f

typedef unsigned long long u64;

// ---- packed f32x2 helpers (sm_103a) ----
__device__ __forceinline__ u64 pk2(float x) {
    u64 d; asm("mov.b64 %0,{%1,%1};" : "=l"(d) : "f"(x)); return d;
}
__device__ __forceinline__ u64 pk(float a, float b) {
    u64 d; asm("mov.b64 %0,{%1,%2};" : "=l"(d) : "f"(a), "f"(b)); return d;
}
__device__ __forceinline__ void upk(u64 v, float& a, float& b) {
    asm("mov.b64 {%0,%1},%2;" : "=f"(a), "=f"(b) : "l"(v));
}
__device__ __forceinline__ u64 f2add(u64 a, u64 b) {
    u64 d; asm("add.rn.f32x2 %0,%1,%2;" : "=l"(d) : "l"(a), "l"(b)); return d;
}
__device__ __forceinline__ u64 f2mul(u64 a, u64 b) {
    u64 d; asm("mul.rn.f32x2 %0,%1,%2;" : "=l"(d) : "l"(a), "l"(b)); return d;
}
__device__ __forceinline__ u64 f2fma(u64 a, u64 b, u64 c) {
    u64 d; asm("fma.rn.f32x2 %0,%1,%2,%3;" : "=l"(d) : "l"(a), "l"(b), "l"(c)); return d;
}
// a - b == fma(b, -1, a), exact
__device__ __forceinline__ u64 f2sub(u64 a, u64 b) {
    return f2fma(b, pk2(-1.0f), a);
}

// packed 8-point DCT: o[u] = sum_x a[x] * cos((2x+1)u pi/16), both lanes
__device__ __forceinline__ void dct8_2(const u64* a, u64* o) {
    const u64 K1 = pk2(C1f), K2 = pk2(C2f), K3 = pk2(C3f), K4 = pk2(C4f);
    const u64 K5 = pk2(C5f), K6 = pk2(C6f), K7 = pk2(C7f);
    const u64 nK1 = pk2(-C1f), nK2 = pk2(-C2f), nK5 = pk2(-C5f), nK7 = pk2(-C7f);
    u64 s0 = f2add(a[0], a[7]), s1 = f2add(a[1], a[6]);
    u64 s2 = f2add(a[2], a[5]), s3 = f2add(a[3], a[4]);
    u64 d0 = f2sub(a[0], a[7]), d1 = f2sub(a[1], a[6]);
    u64 d2 = f2sub(a[2], a[5]), d3 = f2sub(a[3], a[4]);
    u64 f0 = f2add(s0, s3), f1 = f2add(s1, s2);
    u64 e0 = f2sub(s0, s3), e1 = f2sub(s1, s2);
    o[0] = f2add(f0, f1);
    o[4] = f2mul(f2sub(f0, f1), K4);
    o[2] = f2fma(e0, K2, f2mul(e1, K6));
    o[6] = f2fma(e0, K6, f2mul(e1, nK2));
    o[1] = f2fma(d0, K1, f2fma(d1, K3,  f2fma(d2, K5,  f2mul(d3, K7))));
    o[3] = f2fma(d0, K3, f2fma(d1, nK7, f2fma(d2, nK1, f2mul(d3, nK5))));
    o[5] = f2fma(d0, K5, f2fma(d1, nK1, f2fma(d2, K7,  f2mul(d3, K3))));
    o[7] = f2fma(d0, K7, f2fma(d1, nK5, f2fma(d2, K3,  f2mul(d3, nK1))));
}

// packed 8-point IDCT: o[x] = sum_u a[u] * cos((2x+1)u pi/16), both lanes
__device__ __forceinline__ void idct8_2(const u64* a, u64* o) {
    const u64 K1 = pk2(C1f), K2 = pk2(C2f), K3 = pk2(C3f), K4 = pk2(C4f);
    const u64 K5 = pk2(C5f), K6 = pk2(C6f), K7 = pk2(C7f);
    const u64 nK1 = pk2(-C1f), nK2 = pk2(-C2f), nK4 = pk2(-C4f);
    const u64 nK5 = pk2(-C5f), nK6 = pk2(-C6f), nK7 = pk2(-C7f);
    u64 E0 = f2fma(a[2], K2,  f2fma(a[4], K4,  f2fma(a[6], K6,  a[0])));
    u64 E1 = f2fma(a[2], K6,  f2fma(a[4], nK4, f2fma(a[6], nK2, a[0])));
    u64 E2 = f2fma(a[2], nK6, f2fma(a[4], nK4, f2fma(a[6], K2,  a[0])));
    u64 E3 = f2fma(a[2], nK2, f2fma(a[4], K4,  f2fma(a[6], nK6, a[0])));
    u64 O0 = f2fma(a[1], K1, f2fma(a[3], K3,  f2fma(a[5], K5,  f2mul(a[7], K7))));
    u64 O1 = f2fma(a[1], K3, f2fma(a[3], nK7, f2fma(a[5], nK1, f2mul(a[7], nK5))));
    u64 O2 = f2fma(a[1], K5, f2fma(a[3], nK1, f2fma(a[5], K7,  f2mul(a[7], K3))));
    u64 O3 = f2fma(a[1], K7, f2fma(a[3], nK5, f2fma(a[5], K3,  f2mul(a[7], nK1))));
    o[0] = f2add(E0, O0);  o[7] = f2sub(E0, O0);
    o[1] = f2add(E1, O1);  o[6] = f2sub(E1, O1);
    o[2] = f2add(E2, O2);  o[5] = f2sub(E2, O2);
    o[3] = f2add(E3, O3);  o[4] = f2sub(E3, O3);
}

__global__ __launch_bounds__(256)
void diffjpeg_kernel(const float* __restrict__ img,
                     const float* __restrict__ ytab,
                     const float* __restrict__ ctab,
                     float* __restrict__ out)
{
    // pixel planes (16B-aligned rows, conflict-free)
    __shared__ float sY [32 * 36];     // stride 36
    __shared__ float sCb[16 * 20];     // stride 20
    __shared__ float sCr[16 * 20];
    // packed transpose scratch: 12 pair-groups, u64 elems, row stride 10, group stride 88
    __shared__ __align__(16) u64 sT2[12 * 88];
    // packed quant tables: (R,R) and (S,S); R = 0.25*aa/(0.4*tab), S = 0.25*aa*0.4*tab
    __shared__ u64 sR2[2][64];
    __shared__ u64 sS2[2][64];

    const int tid = threadIdx.x;

    if (tid < 128) {
        int ti = tid >> 6, i = tid & 63;
        int u = i >> 3, v = i & 7;
        float aa = (u ? 1.0f : C4f) * (v ? 1.0f : C4f);
        float tq = (ti ? ctab[i] : ytab[i]) * 0.4f;
        sR2[ti][i] = pk2(0.25f * aa / tq);
        sS2[ti][i] = pk2(0.25f * aa * tq);
    }

    // ---------------- front end: load RGB, YCbCr, 2x2 chroma pool ----------
    const int tile = blockIdx.x;
    const int bimg = tile >> 8;            // 256 tiles per image
    const int t    = tile & 255;
    const int ty   = tid >> 3;             // 0..31
    const int txq  = tid & 7;              // 0..7 (x in float4 units)
    const int grow = (t >> 4) * 32 + ty;
    const int gcol = (t & 15) * 32 + txq * 4;

    const float* p = img + (size_t)bimg * 3 * HW + grow * W + gcol;
    float4 r4 = *(const float4*)p;
    float4 g4 = *(const float4*)(p + HW);
    float4 b4 = *(const float4*)(p + 2 * HW);

    float rr[4] = {r4.x, r4.y, r4.z, r4.w};
    float gg[4] = {g4.x, g4.y, g4.z, g4.w};
    float bb[4] = {b4.x, b4.y, b4.z, b4.w};

    float yv[4], cbv[4], crv[4];
    #pragma unroll
    for (int j = 0; j < 4; j++) {
        // coefficients pre-multiplied by 255; Y centered (-128)
        yv [j] = fmaf(rr[j],  76.245f,   fmaf(gg[j],  149.685f,  fmaf(bb[j],  29.07f,    -128.0f)));
        cbv[j] = fmaf(rr[j], -43.02768f, fmaf(gg[j], -84.47232f,       bb[j] * 127.5f));
        crv[j] = fmaf(rr[j], 127.5f,     fmaf(gg[j], -106.76544f,     bb[j] * -20.73456f));
    }

    *(float4*)&sY[ty * 36 + txq * 4] = make_float4(yv[0], yv[1], yv[2], yv[3]);

    // horizontal pair sums in-thread, vertical partner via shfl (row ty^1 = tid^8)
    float cb0 = cbv[0] + cbv[1], cb1 = cbv[2] + cbv[3];
    float cr0 = crv[0] + crv[1], cr1 = crv[2] + crv[3];
    float cb0o = __shfl_xor_sync(0xffffffffu, cb0, 8);
    float cb1o = __shfl_xor_sync(0xffffffffu, cb1, 8);
    float cr0o = __shfl_xor_sync(0xffffffffu, cr0, 8);
    float cr1o = __shfl_xor_sync(0xffffffffu, cr1, 8);
    if (!(ty & 1)) {
        int ci = (ty >> 1) * 20 + txq * 2;
        *(float2*)&sCb[ci] = make_float2(0.25f * (cb0 + cb0o), 0.25f * (cb1 + cb1o));
        *(float2*)&sCr[ci] = make_float2(0.25f * (cr0 + cr0o), 0.25f * (cr1 + cr1o));
    }
    __syncthreads();

    // ---------------- transforms: 12 block-pairs on 96 threads (warps 0-2) --
    // pairs 0..7 = Y (pair = blocks (by, 2q),(by, 2q+1)); 8,9 = Cb; 10,11 = Cr
    if (tid < 96) {
        const int pr = tid >> 3;           // pair 0..11
        const int r  = tid & 7;            // row within block
        float* plane;
        int poff, ti;
        if (pr < 8) {
            plane = sY;  poff = ((pr >> 1) * 8 + r) * 36 + (pr & 1) * 16;  ti = 0;
        } else {
            int c = pr - 8;
            plane = (c < 2) ? sCb : sCr;
            poff = ((c & 1) * 8 + r) * 20;  ti = 1;
        }
        u64* const tg = &sT2[pr * 88];

        u64 a2[8], o2[8];

        // stage 1: load 16 floats (blocks A|B contiguous), pack, row DCT
        {
            float4 v0 = *(const float4*)&plane[poff];
            float4 v1 = *(const float4*)&plane[poff + 4];
            float4 w0 = *(const float4*)&plane[poff + 8];
            float4 w1 = *(const float4*)&plane[poff + 12];
            float A[8] = {v0.x, v0.y, v0.z, v0.w, v1.x, v1.y, v1.z, v1.w};
            float Bv[8] = {w0.x, w0.y, w0.z, w0.w, w1.x, w1.y, w1.z, w1.w};
            #pragma unroll
            for (int i = 0; i < 8; i++) a2[i] = pk(A[i], Bv[i]);
            dct8_2(a2, o2);
            *(ulonglong2*)&tg[r * 10 + 0] = make_ulonglong2(o2[0], o2[1]);
            *(ulonglong2*)&tg[r * 10 + 2] = make_ulonglong2(o2[2], o2[3]);
            *(ulonglong2*)&tg[r * 10 + 4] = make_ulonglong2(o2[4], o2[5]);
            *(ulonglong2*)&tg[r * 10 + 6] = make_ulonglong2(o2[6], o2[7]);
        }
        __syncwarp();

        // stage 2+3: column DCT, quant/dequant (diff_round), column IDCT
        {
            #pragma unroll
            for (int x = 0; x < 8; x++) a2[x] = tg[x * 10 + r];
            dct8_2(a2, o2);
            #pragma unroll
            for (int u = 0; u < 8; u++) {
                u64 R2 = sR2[ti][u * 8 + r];
                u64 S2 = sS2[ti][u * 8 + r];
                u64 tq = f2mul(o2[u], R2);
                float t0, t1;
                upk(tq, t0, t1);
                u64 rq = pk(rintf(t0), rintf(t1));   // round-half-even == jnp.round
                u64 dq = f2sub(tq, rq);
                u64 c3 = f2mul(f2mul(dq, dq), dq);
                a2[u] = f2mul(f2add(rq, c3), S2);
            }
            idct8_2(a2, o2);                          // recon along column v=r
            #pragma unroll
            for (int x = 0; x < 8; x++) tg[x * 10 + r] = o2[x];
        }
        __syncwarp();

        // stage 4: row IDCT, unpack, write both rows back (centered)
        {
            ulonglong2 q0 = *(const ulonglong2*)&tg[r * 10 + 0];
            ulonglong2 q1 = *(const ulonglong2*)&tg[r * 10 + 2];
            ulonglong2 q2 = *(const ulonglong2*)&tg[r * 10 + 4];
            ulonglong2 q3 = *(const ulonglong2*)&tg[r * 10 + 6];
            a2[0] = q0.x; a2[1] = q0.y; a2[2] = q1.x; a2[3] = q1.y;
            a2[4] = q2.x; a2[5] = q2.y; a2[6] = q3.x; a2[7] = q3.y;
            idct8_2(a2, o2);
            float A[8], Bv[8];
            #pragma unroll
            for (int i = 0; i < 8; i++) upk(o2[i], A[i], Bv[i]);
            *(float4*)&plane[poff]      = make_float4(A[0], A[1], A[2], A[3]);
            *(float4*)&plane[poff + 4]  = make_float4(A[4], A[5], A[6], A[7]);
            *(float4*)&plane[poff + 8]  = make_float4(Bv[0], Bv[1], Bv[2], Bv[3]);
            *(float4*)&plane[poff + 12] = make_float4(Bv[4], Bv[5], Bv[6], Bv[7]);
        }
    }
    __syncthreads();

    // ---------------- back end: upsample, YCbCr->RGB, clip, store ----------
    float4 yq = *(const float4*)&sY[ty * 36 + txq * 4];
    const int ci = (ty >> 1) * 20 + txq * 2;
    float2 cbl = *(const float2*)&sCb[ci];
    float2 crl = *(const float2*)&sCr[ci];

    float yb[4] = {yq.x + 128.0f, yq.y + 128.0f, yq.z + 128.0f, yq.w + 128.0f};
    float cbp[4] = {cbl.x, cbl.x, cbl.y, cbl.y};
    float crp[4] = {crl.x, crl.x, crl.y, crl.y};

    float4 orv, ogv, obv;
    float* po_r = &orv.x;
    float* po_g = &ogv.x;
    float* po_b = &obv.x;
    #pragma unroll
    for (int j = 0; j < 4; j++) {
        float ro = fmaf(crp[j],  1.402f,    yb[j]);
        float go = fmaf(crp[j], -0.714136f, fmaf(cbp[j], -0.344136f, yb[j]));
        float bo = fmaf(cbp[j],  1.772f,    yb[j]);
        const float inv255 = 1.0f / 255.0f;
        po_r[j] = fminf(fmaxf(ro, 0.0f), 255.0f) * inv255;
        po_g[j] = fminf(fmaxf(go, 0.0f), 255.0f) * inv255;
        po_b[j] = fminf(fmaxf(bo, 0.0f), 255.0f) * inv255;
    }
    float* q = out + (size_t)bimg * 3 * HW + grow * W + gcol;
    *(float4*)q            = orv;
    *(float4*)(q + HW)     = ogv;
    *(float4*)(q + 2 * HW) = obv;
}

extern "C" void kernel_launch(void* const* d_in, const int* in_sizes, int n_in,
                              void* d_out, int out_size)
{
    const float* img  = (const float*)d_in[0];
    const float* ytab = (const float*)d_in[1];
    const float* ctab = (const float*)d_in[2];
    float* out = (float*)d_out;

    // 32 images * (512/32)^2 tiles = 8192 CTAs
    diffjpeg_kernel<<<8192, 256>>>(img, ytab, ctab, out);
}

// round 8
// speedup vs baseline: 1.0007x; 1.0007x over previous
#include <cuda_runtime.h>

#define HW 262144      // 512*512
#define W  512

// cos(k*pi/16)
#define C1f 0.98078528040323044913f
#define C2f 0.92387953251128675613f
#define C3f 0.83146961230254523708f
#define C4f 0.70710678118654752440f
#define C5f 0.55557023301960222474f
#define C6f 0.38268343236508977173f
#define C7f 0.19509032201612826785f

typedef unsigned long long u64;

// ---- packed f32x2 helpers (sm_103a) ----
__device__ __forceinline__ u64 pk2(float x) {
    u64 d; asm("mov.b64 %0,{%1,%1};" : "=l"(d) : "f"(x)); return d;
}
__device__ __forceinline__ u64 pk(float a, float b) {
    u64 d; asm("mov.b64 %0,{%1,%2};" : "=l"(d) : "f"(a), "f"(b)); return d;
}
__device__ __forceinline__ void upk(u64 v, float& a, float& b) {
    asm("mov.b64 {%0,%1},%2;" : "=f"(a), "=f"(b) : "l"(v));
}
__device__ __forceinline__ u64 f2add(u64 a, u64 b) {
    u64 d; asm("add.rn.f32x2 %0,%1,%2;" : "=l"(d) : "l"(a), "l"(b)); return d;
}
__device__ __forceinline__ u64 f2mul(u64 a, u64 b) {
    u64 d; asm("mul.rn.f32x2 %0,%1,%2;" : "=l"(d) : "l"(a), "l"(b)); return d;
}
__device__ __forceinline__ u64 f2fma(u64 a, u64 b, u64 c) {
    u64 d; asm("fma.rn.f32x2 %0,%1,%2,%3;" : "=l"(d) : "l"(a), "l"(b), "l"(c)); return d;
}
// a - b == fma(b, -1, a), exact
__device__ __forceinline__ u64 f2sub(u64 a, u64 b) {
    return f2fma(b, pk2(-1.0f), a);
}

// packed 8-point DCT: o[u] = sum_x a[x] * cos((2x+1)u pi/16), both lanes
__device__ __forceinline__ void dct8_2(const u64* a, u64* o) {
    const u64 K1 = pk2(C1f), K2 = pk2(C2f), K3 = pk2(C3f), K4 = pk2(C4f);
    const u64 K5 = pk2(C5f), K6 = pk2(C6f), K7 = pk2(C7f);
    const u64 nK1 = pk2(-C1f), nK2 = pk2(-C2f), nK5 = pk2(-C5f), nK7 = pk2(-C7f);
    u64 s0 = f2add(a[0], a[7]), s1 = f2add(a[1], a[6]);
    u64 s2 = f2add(a[2], a[5]), s3 = f2add(a[3], a[4]);
    u64 d0 = f2sub(a[0], a[7]), d1 = f2sub(a[1], a[6]);
    u64 d2 = f2sub(a[2], a[5]), d3 = f2sub(a[3], a[4]);
    u64 f0 = f2add(s0, s3), f1 = f2add(s1, s2);
    u64 e0 = f2sub(s0, s3), e1 = f2sub(s1, s2);
    o[0] = f2add(f0, f1);
    o[4] = f2mul(f2sub(f0, f1), K4);
    o[2] = f2fma(e0, K2, f2mul(e1, K6));
    o[6] = f2fma(e0, K6, f2mul(e1, nK2));
    o[1] = f2fma(d0, K1, f2fma(d1, K3,  f2fma(d2, K5,  f2mul(d3, K7))));
    o[3] = f2fma(d0, K3, f2fma(d1, nK7, f2fma(d2, nK1, f2mul(d3, nK5))));
    o[5] = f2fma(d0, K5, f2fma(d1, nK1, f2fma(d2, K7,  f2mul(d3, K3))));
    o[7] = f2fma(d0, K7, f2fma(d1, nK5, f2fma(d2, K3,  f2mul(d3, nK1))));
}

// packed 8-point IDCT: o[x] = sum_u a[u] * cos((2x+1)u pi/16), both lanes
__device__ __forceinline__ void idct8_2(const u64* a, u64* o) {
    const u64 K1 = pk2(C1f), K2 = pk2(C2f), K3 = pk2(C3f), K4 = pk2(C4f);
    const u64 K5 = pk2(C5f), K6 = pk2(C6f), K7 = pk2(C7f);
    const u64 nK1 = pk2(-C1f), nK2 = pk2(-C2f), nK4 = pk2(-C4f);
    const u64 nK5 = pk2(-C5f), nK6 = pk2(-C6f), nK7 = pk2(-C7f);
    u64 E0 = f2fma(a[2], K2,  f2fma(a[4], K4,  f2fma(a[6], K6,  a[0])));
    u64 E1 = f2fma(a[2], K6,  f2fma(a[4], nK4, f2fma(a[6], nK2, a[0])));
    u64 E2 = f2fma(a[2], nK6, f2fma(a[4], nK4, f2fma(a[6], K2,  a[0])));
    u64 E3 = f2fma(a[2], nK2, f2fma(a[4], K4,  f2fma(a[6], nK6, a[0])));
    u64 O0 = f2fma(a[1], K1, f2fma(a[3], K3,  f2fma(a[5], K5,  f2mul(a[7], K7))));
    u64 O1 = f2fma(a[1], K3, f2fma(a[3], nK7, f2fma(a[5], nK1, f2mul(a[7], nK5))));
    u64 O2 = f2fma(a[1], K5, f2fma(a[3], nK1, f2fma(a[5], K7,  f2mul(a[7], K3))));
    u64 O3 = f2fma(a[1], K7, f2fma(a[3], nK5, f2fma(a[5], K3,  f2mul(a[7], nK1))));
    o[0] = f2add(E0, O0);  o[7] = f2sub(E0, O0);
    o[1] = f2add(E1, O1);  o[6] = f2sub(E1, O1);
    o[2] = f2add(E2, O2);  o[5] = f2sub(E2, O2);
    o[3] = f2add(E3, O3);  o[4] = f2sub(E3, O3);
}

__global__ __launch_bounds__(256)
void diffjpeg_kernel(const float* __restrict__ img,
                     const float* __restrict__ ytab,
                     const float* __restrict__ ctab,
                     float* __restrict__ out)
{
    // pixel planes: 32 rows x 64 cols (Y, stride 68) and 16 x 32 chroma (stride 36)
    __shared__ float sY [32 * 68];
    __shared__ float sCb[16 * 36];
    __shared__ float sCr[16 * 36];
    // packed transpose scratch: 24 pair-groups, u64 elems, row stride 10, group stride 88
    __shared__ __align__(16) u64 sT2[24 * 88];
    // packed quant tables: (R,R),(S,S); R = 0.25*aa/(0.4*tab), S = 0.25*aa*0.4*tab
    __shared__ u64 sR2[2][64];
    __shared__ u64 sS2[2][64];

    const int tid = threadIdx.x;

    if (tid < 128) {
        int ti = tid >> 6, i = tid & 63;
        int u = i >> 3, v = i & 7;
        float aa = (u ? 1.0f : C4f) * (v ? 1.0f : C4f);
        float tq = (ti ? ctab[i] : ytab[i]) * 0.4f;
        sR2[ti][i] = pk2(0.25f * aa / tq);
        sS2[ti][i] = pk2(0.25f * aa * tq);
    }

    // ---------------- front end: tile = 32 rows x 64 cols -------------------
    const int tile = blockIdx.x;
    const int bimg = tile >> 7;            // 128 tiles per image
    const int t    = tile & 127;           // 16 x 8 tiles
    const int ty   = tid >> 3;             // 0..31  (row in tile)
    const int txq  = tid & 7;              // 0..7   (x in float4 units)
    const int grow = (t >> 3) * 32 + ty;
    const int gcol = (t & 7) * 64 + txq * 4;

    const float* p = img + (size_t)bimg * 3 * HW + grow * W + gcol;

    const u64 KYr = pk2(76.245f),    KYg = pk2(149.685f),    KYb = pk2(29.07f), Kn128 = pk2(-128.0f);
    const u64 KBr = pk2(-43.02768f), KBg = pk2(-84.47232f),  KBb = pk2(127.5f);
    const u64 KRr = pk2(127.5f),     KRg = pk2(-106.76544f), KRb = pk2(-20.73456f);

    #pragma unroll
    for (int h = 0; h < 2; h++) {
        const int off = 32 * h;
        float4 r4 = *(const float4*)(p + off);
        float4 g4 = *(const float4*)(p + HW + off);
        float4 b4 = *(const float4*)(p + 2 * HW + off);
        u64 rlo = pk(r4.x, r4.y), rhi = pk(r4.z, r4.w);
        u64 glo = pk(g4.x, g4.y), ghi = pk(g4.z, g4.w);
        u64 blo = pk(b4.x, b4.y), bhi = pk(b4.z, b4.w);

        // Y (centered): coeffs pre-multiplied by 255, -128 folded in
        u64 ylo = f2fma(rlo, KYr, f2fma(glo, KYg, f2fma(blo, KYb, Kn128)));
        u64 yhi = f2fma(rhi, KYr, f2fma(ghi, KYg, f2fma(bhi, KYb, Kn128)));
        float y0, y1, y2, y3; upk(ylo, y0, y1); upk(yhi, y2, y3);
        *(float4*)&sY[ty * 68 + txq * 4 + off] = make_float4(y0, y1, y2, y3);

        // chroma (centered; +128/-128 cancel)
        u64 cblo = f2fma(rlo, KBr, f2fma(glo, KBg, f2mul(blo, KBb)));
        u64 cbhi = f2fma(rhi, KBr, f2fma(ghi, KBg, f2mul(bhi, KBb)));
        u64 crlo = f2fma(rlo, KRr, f2fma(glo, KRg, f2mul(blo, KRb)));
        u64 crhi = f2fma(rhi, KRr, f2fma(ghi, KRg, f2mul(bhi, KRb)));
        float a0, a1, b0, b1;
        upk(cblo, a0, a1); upk(cbhi, b0, b1);
        float cb0 = a0 + a1, cb1 = b0 + b1;        // horizontal 2:1
        upk(crlo, a0, a1); upk(crhi, b0, b1);
        float cr0 = a0 + a1, cr1 = b0 + b1;
        // vertical partner: row ty^1 == lane^8
        cb0 += __shfl_xor_sync(0xffffffffu, cb0, 8);
        cb1 += __shfl_xor_sync(0xffffffffu, cb1, 8);
        cr0 += __shfl_xor_sync(0xffffffffu, cr0, 8);
        cr1 += __shfl_xor_sync(0xffffffffu, cr1, 8);
        if (!(ty & 1)) {
            int ci = (ty >> 1) * 36 + txq * 2 + 16 * h;
            *(float2*)&sCb[ci] = make_float2(0.25f * cb0, 0.25f * cb1);
            *(float2*)&sCr[ci] = make_float2(0.25f * cr0, 0.25f * cr1);
        }
    }
    __syncthreads();

    // ---------------- transforms: 24 packed block-pairs on 192 threads ------
    // pr 0..15 = Y pairs (4 rows x 4 pair-cols of 16 px), 16..19 = Cb, 20..23 = Cr
    if (tid < 192) {
        const int pr = tid >> 3;           // pair 0..23 (uniform per warp: 4/warp)
        const int r  = tid & 7;            // row within block
        float* plane;
        int poff, ti;
        if (pr < 16) {
            plane = sY;  poff = ((pr >> 2) * 8 + r) * 68 + (pr & 3) * 16;  ti = 0;
        } else {
            int c = pr - 16;               // 0..7 (0-3 Cb, 4-7 Cr)
            plane = (c < 4) ? sCb : sCr;
            int cc = c & 3;
            poff = (((cc >> 1) * 8 + r) * 36) + (cc & 1) * 16;  ti = 1;
        }
        u64* const tg = &sT2[pr * 88];

        u64 a2[8], o2[8];

        // stage 1: load 16 floats (blocks A|B contiguous), pack, row DCT
        {
            float4 v0 = *(const float4*)&plane[poff];
            float4 v1 = *(const float4*)&plane[poff + 4];
            float4 w0 = *(const float4*)&plane[poff + 8];
            float4 w1 = *(const float4*)&plane[poff + 12];
            float A[8]  = {v0.x, v0.y, v0.z, v0.w, v1.x, v1.y, v1.z, v1.w};
            float Bv[8] = {w0.x, w0.y, w0.z, w0.w, w1.x, w1.y, w1.z, w1.w};
            #pragma unroll
            for (int i = 0; i < 8; i++) a2[i] = pk(A[i], Bv[i]);
            dct8_2(a2, o2);
            *(ulonglong2*)&tg[r * 10 + 0] = make_ulonglong2(o2[0], o2[1]);
            *(ulonglong2*)&tg[r * 10 + 2] = make_ulonglong2(o2[2], o2[3]);
            *(ulonglong2*)&tg[r * 10 + 4] = make_ulonglong2(o2[4], o2[5]);
            *(ulonglong2*)&tg[r * 10 + 6] = make_ulonglong2(o2[6], o2[7]);
        }
        __syncwarp();

        // stage 2+3: column DCT, quant/dequant (diff_round), column IDCT
        {
            #pragma unroll
            for (int x = 0; x < 8; x++) a2[x] = tg[x * 10 + r];
            dct8_2(a2, o2);
            #pragma unroll
            for (int u = 0; u < 8; u++) {
                u64 R2 = sR2[ti][u * 8 + r];
                u64 S2 = sS2[ti][u * 8 + r];
                u64 tq = f2mul(o2[u], R2);
                float t0, t1;
                upk(tq, t0, t1);
                u64 rq = pk(rintf(t0), rintf(t1));   // round-half-even == jnp.round
                u64 dq = f2sub(tq, rq);
                u64 c3 = f2mul(f2mul(dq, dq), dq);
                a2[u] = f2mul(f2add(rq, c3), S2);
            }
            idct8_2(a2, o2);                          // recon along column v=r
            #pragma unroll
            for (int x = 0; x < 8; x++) tg[x * 10 + r] = o2[x];
        }
        __syncwarp();

        // stage 4: row IDCT, unpack, write both block rows back (centered)
        {
            ulonglong2 q0 = *(const ulonglong2*)&tg[r * 10 + 0];
            ulonglong2 q1 = *(const ulonglong2*)&tg[r * 10 + 2];
            ulonglong2 q2 = *(const ulonglong2*)&tg[r * 10 + 4];
            ulonglong2 q3 = *(const ulonglong2*)&tg[r * 10 + 6];
            a2[0] = q0.x; a2[1] = q0.y; a2[2] = q1.x; a2[3] = q1.y;
            a2[4] = q2.x; a2[5] = q2.y; a2[6] = q3.x; a2[7] = q3.y;
            idct8_2(a2, o2);
            float A[8], Bv[8];
            #pragma unroll
            for (int i = 0; i < 8; i++) upk(o2[i], A[i], Bv[i]);
            *(float4*)&plane[poff]      = make_float4(A[0], A[1], A[2], A[3]);
            *(float4*)&plane[poff + 4]  = make_float4(A[4], A[5], A[6], A[7]);
            *(float4*)&plane[poff + 8]  = make_float4(Bv[0], Bv[1], Bv[2], Bv[3]);
            *(float4*)&plane[poff + 12] = make_float4(Bv[4], Bv[5], Bv[6], Bv[7]);
        }
    }
    __syncthreads();

    // ---------------- back end: upsample, YCbCr->RGB, clip, store ----------
    float* q = out + (size_t)bimg * 3 * HW + grow * W + gcol;
    #pragma unroll
    for (int h = 0; h < 2; h++) {
        const int off = 32 * h;
        float4 yq = *(const float4*)&sY[ty * 68 + txq * 4 + off];
        const int ci = (ty >> 1) * 36 + txq * 2 + 16 * h;
        float2 cbl = *(const float2*)&sCb[ci];
        float2 crl = *(const float2*)&sCr[ci];

        float yb[4]  = {yq.x + 128.0f, yq.y + 128.0f, yq.z + 128.0f, yq.w + 128.0f};
        float cbp[4] = {cbl.x, cbl.x, cbl.y, cbl.y};
        float crp[4] = {crl.x, crl.x, crl.y, crl.y};

        float4 orv, ogv, obv;
        float* po_r = &orv.x;
        float* po_g = &ogv.x;
        float* po_b = &obv.x;
        #pragma unroll
        for (int j = 0; j < 4; j++) {
            float ro = fmaf(crp[j],  1.402f,    yb[j]);
            float go = fmaf(crp[j], -0.714136f, fmaf(cbp[j], -0.344136f, yb[j]));
            float bo = fmaf(cbp[j],  1.772f,    yb[j]);
            const float inv255 = 1.0f / 255.0f;
            po_r[j] = fminf(fmaxf(ro, 0.0f), 255.0f) * inv255;
            po_g[j] = fminf(fmaxf(go, 0.0f), 255.0f) * inv255;
            po_b[j] = fminf(fmaxf(bo, 0.0f), 255.0f) * inv255;
        }
        *(float4*)(q + off)          = orv;
        *(float4*)(q + HW + off)     = ogv;
        *(float4*)(q + 2 * HW + off) = obv;
    }
}

extern "C" void kernel_launch(void* const* d_in, const int* in_sizes, int n_in,
                              void* d_out, int out_size)
{
    const float* img  = (const float*)d_in[0];
    const float* ytab = (const float*)d_in[1];
    const float* ctab = (const float*)d_in[2];
    float* out = (float*)d_out;

    // 32 images * (512/32)*(512/64) tiles = 4096 CTAs
    diffjpeg_kernel<<<4096, 256>>>(img, ytab, ctab, out);
}